// round 13
// baseline (speedup 1.0000x reference)
#include <cuda_runtime.h>
#include <cuda_fp16.h>
#include <mma.h>

using namespace nvcuda;

#define N_NODES 100000
#define N_EDGES 1600000

typedef unsigned long long ull;

// ---------------- scratch (__device__ globals; no allocation allowed) ----------------
__device__ ull   g_pack[N_NODES];     // (cnt << 42) | round(sum_ew * 2^22)
__device__ float g_dis[N_NODES];
__device__ int   g_cnt[N_NODES];
__device__ int   g_rowptr[N_NODES];
__device__ int   g_fill[N_NODES];
__device__ int   g_col[N_EDGES];
__device__ float g_val[N_EDGES];
__device__ int   g_is64;
__device__ int   g_total;
__device__ float g_W45[256 * 3];
__device__ float g_b45[3];
__device__ __half g_hx[(size_t)N_NODES * 128];
__device__ __half g_hA[(size_t)N_NODES * 256];
__device__ __half g_hB[(size_t)N_NODES * 256];
__device__ __half g_hW1[128 * 64];
__device__ __half g_hW2[64 * 128];
__device__ __half g_hW3[128 * 256];
__device__ float4 g_proj[N_NODES];

#define EW_SCALE 4194304.0f           // 2^22
#define EW_MASK  ((1ULL << 42) - 1ULL)
#define CNT_ONE  (1ULL << 42)

// ---------------- fused init + dtype detection + proj zero ----------------
__global__ void k_initdet(const long long* __restrict__ ei) {
    __shared__ int bigfound;
    int i = blockIdx.x * blockDim.x + threadIdx.x;
    if (i < N_NODES) {
        g_pack[i] = 0ull;
        g_proj[i] = make_float4(0.f, 0.f, 0.f, 0.f);
    }
    if (blockIdx.x == 0) {
        if (threadIdx.x == 0) { bigfound = 0; g_total = 0; }
        __syncthreads();
        bool big = false;
#pragma unroll
        for (int j = 0; j < 8; j++) {
            ull v = (ull)ei[threadIdx.x * 8 + j];
            if (v >= (ull)N_NODES) big = true;
        }
        if (big) bigfound = 1;
        __syncthreads();
        if (threadIdx.x == 0) g_is64 = bigfound ? 0 : 1;
    }
}

__device__ __forceinline__ void decode_edge(const void* eiv, int e, int& s, int& d) {
    if (g_is64) {
        const long long* ei = (const long long*)eiv;
        s = (int)ei[e];
        d = (int)ei[N_EDGES + e];
    } else {
        const int* ei = (const int*)eiv;
        s = ei[e];
        d = ei[N_EDGES + e];
    }
}

// one ull atomic per edge (count + fixed-point weighted degree), 2 edges/thread
__global__ void k_decdeg(const void* __restrict__ eiv, const float* __restrict__ ew) {
    int e0 = (blockIdx.x * blockDim.x + threadIdx.x) * 2;
    if (e0 >= N_EDGES) return;
    int s0, d0, s1, d1;
    decode_edge(eiv, e0, s0, d0);
    ull x0 = CNT_ONE | (ull)(ew[e0] * EW_SCALE + 0.5f);
    bool two = (e0 + 1 < N_EDGES);
    if (two) {
        decode_edge(eiv, e0 + 1, s1, d1);
        ull x1 = CNT_ONE | (ull)(ew[e0 + 1] * EW_SCALE + 0.5f);
        atomicAdd(&g_pack[d0], x0);
        atomicAdd(&g_pack[d1], x1);
    } else {
        atomicAdd(&g_pack[d0], x0);
    }
}

// fused: unpack deg/cnt, dis = rsqrt(deg), CSR slot allocation (block scan + 1 atomic)
__global__ void k_disalloc() {
    __shared__ int s[256];
    __shared__ int sbase;
    int tid = threadIdx.x;
    int i = blockIdx.x * 256 + tid;
    int c = 0;
    if (i < N_NODES) {
        ull pk = g_pack[i];
        c = (int)(pk >> 42);
        float deg = 1.0f + (float)(pk & EW_MASK) * (1.0f / EW_SCALE);
        g_dis[i] = rsqrtf(deg);
        g_cnt[i] = c;
    }
    s[tid] = c;
    __syncthreads();
    for (int off = 1; off < 256; off <<= 1) {
        int t = (tid >= off) ? s[tid - off] : 0;
        __syncthreads();
        s[tid] += t;
        __syncthreads();
    }
    if (tid == 255) sbase = atomicAdd(&g_total, s[255]);
    __syncthreads();
    if (i < N_NODES) {
        int r = sbase + s[tid] - c;
        g_rowptr[i] = r;
        g_fill[i] = r;
    }
}

// 2 edges per thread
__global__ void k_build(const void* __restrict__ eiv, const float* __restrict__ ew) {
    int e0 = (blockIdx.x * blockDim.x + threadIdx.x) * 2;
    if (e0 >= N_EDGES) return;
#pragma unroll
    for (int q = 0; q < 2; q++) {
        int e = e0 + q;
        if (e >= N_EDGES) break;
        int s, d;
        decode_edge(eiv, e, s, d);
        float nm = g_dis[s] * ew[e] * g_dis[d];
        int p = atomicAdd(&g_fill[d], 1);
        g_col[p] = s;
        g_val[p] = nm;
    }
}

// parallel fold: W45[k][c] = sum_j W4[k][j] * Wout[j][c]; one warp per output
__global__ void k_w45(const float* __restrict__ W4, const float* __restrict__ b4,
                      const float* __restrict__ Wout, const float* __restrict__ bout) {
    int gw = (blockIdx.x * blockDim.x + threadIdx.x) >> 5;
    int lane = threadIdx.x & 31;
    if (gw < 768) {
        int k = gw / 3, c = gw % 3;
        float s = 0.f;
#pragma unroll
        for (int j = lane; j < 256; j += 32)
            s += W4[k * 256 + j] * Wout[j * 3 + c];
#pragma unroll
        for (int off = 16; off; off >>= 1)
            s += __shfl_down_sync(0xffffffffu, s, off);
        if (lane == 0) g_W45[gw] = s;
    } else if (gw < 771) {
        int c = gw - 768;
        float s = 0.f;
#pragma unroll
        for (int j = lane; j < 256; j += 32)
            s += b4[j] * Wout[j * 3 + c];
#pragma unroll
        for (int off = 16; off; off >>= 1)
            s += __shfl_down_sync(0xffffffffu, s, off);
        if (lane == 0) g_b45[c] = s + bout[c];
    }
}

// ---------------- fused fp32->fp16: x (12.8M) then W1/W2/W3 (49152) ----------------
#define NX (N_NODES * 128)
__global__ void k_cvtall(const float* __restrict__ x, const float* __restrict__ W1,
                         const float* __restrict__ W2, const float* __restrict__ W3,
                         __half* __restrict__ hx, __half* __restrict__ h1,
                         __half* __restrict__ h2, __half* __restrict__ h3) {
    int i = (blockIdx.x * blockDim.x + threadIdx.x) * 8;
    const float* in;
    __half* out;
    if (i < NX) { in = x; out = hx; }
    else {
        int w = i - NX;
        if (w < 8192) { in = W1; out = h1; i = w; }
        else if (w < 16384) { in = W2; out = h2; i = w - 8192; }
        else if (w < 49152) { in = W3; out = h3; i = w - 16384; }
        else return;
    }
    float4 a = *(const float4*)&in[i];
    float4 b = *(const float4*)&in[i + 4];
    __half2 q0 = __floats2half2_rn(a.x, a.y);
    __half2 q1 = __floats2half2_rn(a.z, a.w);
    __half2 q2 = __floats2half2_rn(b.x, b.y);
    __half2 q3 = __floats2half2_rn(b.z, b.w);
    uint4 pk;
    pk.x = *(unsigned*)&q0; pk.y = *(unsigned*)&q1;
    pk.z = *(unsigned*)&q2; pk.w = *(unsigned*)&q3;
    *(uint4*)&out[i] = pk;
}

// ---------------- HMMA GEMM (wmma): double-buffered, BK=32, fp16 output ----------------
__global__ void k_hgemm(const __half* __restrict__ A, const __half* __restrict__ W,
                        const float* __restrict__ bias, __half* __restrict__ C,
                        int din, int dout, int relu) {
    __shared__ __half As[2][128][40];
    __shared__ __half Bs[2][32][72];
    __shared__ float Es[8][256];

    int tid = threadIdx.x;
    int lane = tid & 31;
    int wid = tid >> 5;
    int warp_m = wid & 3;
    int warp_n = wid >> 2;
    int row0 = blockIdx.x * 128;
    int col0 = blockIdx.y * 64;

    int ar0 = tid >> 1, ac0 = (tid & 1) * 8;
    int br = tid >> 3, bc = (tid & 7) * 8;

    wmma::fragment<wmma::accumulator, 16, 16, 16, float> acc[2][2];
#pragma unroll
    for (int i = 0; i < 2; i++)
#pragma unroll
        for (int j = 0; j < 2; j++) wmma::fill_fragment(acc[i][j], 0.f);

    int nk = din >> 5;

    {
        uint4 v0 = make_uint4(0, 0, 0, 0), v1 = v0;
        if (row0 + ar0 < N_NODES) {
            v0 = *(const uint4*)&A[(size_t)(row0 + ar0) * din + ac0];
            v1 = *(const uint4*)&A[(size_t)(row0 + ar0) * din + ac0 + 16];
        }
        *(uint4*)&As[0][ar0][ac0] = v0;
        *(uint4*)&As[0][ar0][ac0 + 16] = v1;
        *(uint4*)&Bs[0][br][bc] = *(const uint4*)&W[(size_t)br * dout + col0 + bc];
    }
    __syncthreads();

    for (int kt = 0; kt < nk; kt++) {
        int cur = kt & 1;
        bool more = (kt + 1 < nk);
        uint4 p0, p1, pb;
        if (more) {
            int k0 = (kt + 1) << 5;
            p0 = make_uint4(0, 0, 0, 0); p1 = p0;
            if (row0 + ar0 < N_NODES) {
                p0 = *(const uint4*)&A[(size_t)(row0 + ar0) * din + k0 + ac0];
                p1 = *(const uint4*)&A[(size_t)(row0 + ar0) * din + k0 + ac0 + 16];
            }
            pb = *(const uint4*)&W[(size_t)(k0 + br) * dout + col0 + bc];
        }
#pragma unroll
        for (int ks = 0; ks < 2; ks++) {
            wmma::fragment<wmma::matrix_a, 16, 16, 16, __half, wmma::row_major> af[2];
            wmma::fragment<wmma::matrix_b, 16, 16, 16, __half, wmma::row_major> bf[2];
#pragma unroll
            for (int i = 0; i < 2; i++)
                wmma::load_matrix_sync(af[i], &As[cur][warp_m * 32 + i * 16][ks * 16], 40);
#pragma unroll
            for (int j = 0; j < 2; j++)
                wmma::load_matrix_sync(bf[j], &Bs[cur][ks * 16][warp_n * 32 + j * 16], 72);
#pragma unroll
            for (int i = 0; i < 2; i++)
#pragma unroll
                for (int j = 0; j < 2; j++)
                    wmma::mma_sync(acc[i][j], af[i], bf[j], acc[i][j]);
        }
        if (more) {
            int nxt = cur ^ 1;
            *(uint4*)&As[nxt][ar0][ac0] = p0;
            *(uint4*)&As[nxt][ar0][ac0 + 16] = p1;
            *(uint4*)&Bs[nxt][br][bc] = pb;
            __syncthreads();
        }
    }

#pragma unroll
    for (int i = 0; i < 2; i++) {
#pragma unroll
        for (int j = 0; j < 2; j++) {
            wmma::store_matrix_sync(&Es[wid][0], acc[i][j], 16, wmma::mem_row_major);
            __syncwarp();
            int r = lane >> 1, c = (lane & 1) * 8;
            int gr = row0 + warp_m * 32 + i * 16 + r;
            int gc = col0 + warp_n * 32 + j * 16 + c;
            if (gr < N_NODES) {
                float v[8];
#pragma unroll
                for (int t = 0; t < 8; t++) {
                    float f = Es[wid][r * 16 + c + t];
                    if (bias) f += bias[gc + t];
                    if (relu) f = fmaxf(f, 0.f);
                    v[t] = f;
                }
                __half2 h0 = __floats2half2_rn(v[0], v[1]);
                __half2 h1 = __floats2half2_rn(v[2], v[3]);
                __half2 h2 = __floats2half2_rn(v[4], v[5]);
                __half2 h3 = __floats2half2_rn(v[6], v[7]);
                uint4 pk;
                pk.x = *(unsigned*)&h0; pk.y = *(unsigned*)&h1;
                pk.z = *(unsigned*)&h2; pk.w = *(unsigned*)&h3;
                *(uint4*)&C[(size_t)gr * dout + gc] = pk;
            }
            __syncwarp();
        }
    }
}

// ---------------- GEMM3 fused with projection: (relu(A@W3+b3)) @ W45 -> atomicAdd g_proj ----------------
__global__ void k_hgemm_proj(const __half* __restrict__ A, const __half* __restrict__ W,
                             const float* __restrict__ bias) {
    const int din = 128, dout = 256;
    __shared__ __half As[2][128][40];
    __shared__ __half Bs[2][32][72];
    __shared__ float Es[8][256];

    int tid = threadIdx.x;
    int lane = tid & 31;
    int wid = tid >> 5;
    int warp_m = wid & 3;
    int warp_n = wid >> 2;
    int row0 = blockIdx.x * 128;
    int col0 = blockIdx.y * 64;

    int ar0 = tid >> 1, ac0 = (tid & 1) * 8;
    int br = tid >> 3, bc = (tid & 7) * 8;

    wmma::fragment<wmma::accumulator, 16, 16, 16, float> acc[2][2];
#pragma unroll
    for (int i = 0; i < 2; i++)
#pragma unroll
        for (int j = 0; j < 2; j++) wmma::fill_fragment(acc[i][j], 0.f);

    int nk = din >> 5;

    {
        uint4 v0 = make_uint4(0, 0, 0, 0), v1 = v0;
        if (row0 + ar0 < N_NODES) {
            v0 = *(const uint4*)&A[(size_t)(row0 + ar0) * din + ac0];
            v1 = *(const uint4*)&A[(size_t)(row0 + ar0) * din + ac0 + 16];
        }
        *(uint4*)&As[0][ar0][ac0] = v0;
        *(uint4*)&As[0][ar0][ac0 + 16] = v1;
        *(uint4*)&Bs[0][br][bc] = *(const uint4*)&W[(size_t)br * dout + col0 + bc];
    }
    __syncthreads();

    for (int kt = 0; kt < nk; kt++) {
        int cur = kt & 1;
        bool more = (kt + 1 < nk);
        uint4 p0, p1, pb;
        if (more) {
            int k0 = (kt + 1) << 5;
            p0 = make_uint4(0, 0, 0, 0); p1 = p0;
            if (row0 + ar0 < N_NODES) {
                p0 = *(const uint4*)&A[(size_t)(row0 + ar0) * din + k0 + ac0];
                p1 = *(const uint4*)&A[(size_t)(row0 + ar0) * din + k0 + ac0 + 16];
            }
            pb = *(const uint4*)&W[(size_t)(k0 + br) * dout + col0 + bc];
        }
#pragma unroll
        for (int ks = 0; ks < 2; ks++) {
            wmma::fragment<wmma::matrix_a, 16, 16, 16, __half, wmma::row_major> af[2];
            wmma::fragment<wmma::matrix_b, 16, 16, 16, __half, wmma::row_major> bf[2];
#pragma unroll
            for (int i = 0; i < 2; i++)
                wmma::load_matrix_sync(af[i], &As[cur][warp_m * 32 + i * 16][ks * 16], 40);
#pragma unroll
            for (int j = 0; j < 2; j++)
                wmma::load_matrix_sync(bf[j], &Bs[cur][ks * 16][warp_n * 32 + j * 16], 72);
#pragma unroll
            for (int i = 0; i < 2; i++)
#pragma unroll
                for (int j = 0; j < 2; j++)
                    wmma::mma_sync(acc[i][j], af[i], bf[j], acc[i][j]);
        }
        if (more) {
            int nxt = cur ^ 1;
            *(uint4*)&As[nxt][ar0][ac0] = p0;
            *(uint4*)&As[nxt][ar0][ac0 + 16] = p1;
            *(uint4*)&Bs[nxt][br][bc] = pb;
            __syncthreads();
        }
    }

    // epilogue: bias + relu + project 64 cols against W45, atomic accumulate
    int r = lane >> 1, cbase = (lane & 1) * 8;
#pragma unroll
    for (int i = 0; i < 2; i++) {
        float s0 = 0.f, s1 = 0.f, s2 = 0.f;
        int gr = row0 + warp_m * 32 + i * 16 + r;
#pragma unroll
        for (int j = 0; j < 2; j++) {
            wmma::store_matrix_sync(&Es[wid][0], acc[i][j], 16, wmma::mem_row_major);
            __syncwarp();
            int gc = col0 + warp_n * 32 + j * 16 + cbase;
#pragma unroll
            for (int t = 0; t < 8; t++) {
                float f = Es[wid][r * 16 + cbase + t] + bias[gc + t];
                f = fmaxf(f, 0.f);
                s0 += f * g_W45[(gc + t) * 3 + 0];
                s1 += f * g_W45[(gc + t) * 3 + 1];
                s2 += f * g_W45[(gc + t) * 3 + 2];
            }
            __syncwarp();
        }
        s0 += __shfl_xor_sync(0xffffffffu, s0, 1);
        s1 += __shfl_xor_sync(0xffffffffu, s1, 1);
        s2 += __shfl_xor_sync(0xffffffffu, s2, 1);
        if ((lane & 1) == 0 && gr < N_NODES) {
            atomicAdd(&g_proj[gr].x, s0);
            atomicAdd(&g_proj[gr].y, s1);
            atomicAdd(&g_proj[gr].z, s2);
        }
    }
}

// ---------------- aggregation D=64 fp16: 4 edges per warp (8 lanes x 16B each) ----------------
template <bool BIAS, bool RELU>
__global__ void k_agg64(const __half* __restrict__ H, const float* __restrict__ bias,
                        __half* __restrict__ out) {
    int warp = (blockIdx.x * blockDim.x + threadIdx.x) >> 5;
    int lane = threadIdx.x & 31;
    if (warp >= N_NODES) return;
    int grp = lane >> 3, gl = lane & 7;
    const uint4* H4 = (const uint4*)H;

    float a[8];
#pragma unroll
    for (int j = 0; j < 8; j++) a[j] = 0.f;

    if (grp == 0) {
        float selfn = g_dis[warp];
        selfn *= selfn;
        uint4 v = H4[(size_t)warp * 8 + gl];
        const __half2* h2 = (const __half2*)&v;
#pragma unroll
        for (int j = 0; j < 4; j++) {
            float2 f = __half22float2(h2[j]);
            a[2 * j] = f.x * selfn;
            a[2 * j + 1] = f.y * selfn;
        }
    }

    int s = g_rowptr[warp];
    int e = s + g_cnt[warp];
    for (int p = s + grp; p < e; p += 4) {
        int src = __ldg(&g_col[p]);
        float w = __ldg(&g_val[p]);
        uint4 v = __ldg(&H4[(size_t)src * 8 + gl]);
        const __half2* h2 = (const __half2*)&v;
#pragma unroll
        for (int j = 0; j < 4; j++) {
            float2 f = __half22float2(h2[j]);
            a[2 * j] += f.x * w;
            a[2 * j + 1] += f.y * w;
        }
    }
    __syncwarp();
#pragma unroll
    for (int j = 0; j < 8; j++) {
        a[j] += __shfl_xor_sync(0xffffffffu, a[j], 8);
        a[j] += __shfl_xor_sync(0xffffffffu, a[j], 16);
    }
    if (grp == 0) {
#pragma unroll
        for (int j = 0; j < 8; j++) {
            if (BIAS) a[j] += bias[gl * 8 + j];
            if (RELU) a[j] = fmaxf(a[j], 0.f);
        }
        __half2 h0 = __floats2half2_rn(a[0], a[1]);
        __half2 h1 = __floats2half2_rn(a[2], a[3]);
        __half2 h2o = __floats2half2_rn(a[4], a[5]);
        __half2 h3 = __floats2half2_rn(a[6], a[7]);
        uint4 pk;
        pk.x = *(unsigned*)&h0; pk.y = *(unsigned*)&h1;
        pk.z = *(unsigned*)&h2o; pk.w = *(unsigned*)&h3;
        ((uint4*)out)[(size_t)warp * 8 + gl] = pk;
    }
}

// ---------------- aggregation D=128 fp16 in/out: 2 edges per warp (16 lanes x 16B) ----------------
__global__ void k_agg128(const __half* __restrict__ H, __half* __restrict__ out) {
    int warp = (blockIdx.x * blockDim.x + threadIdx.x) >> 5;
    int lane = threadIdx.x & 31;
    if (warp >= N_NODES) return;
    int half = lane >> 4, hl = lane & 15;
    const uint4* H4 = (const uint4*)H;

    float a[8];
#pragma unroll
    for (int j = 0; j < 8; j++) a[j] = 0.f;

    if (half == 0) {
        float selfn = g_dis[warp];
        selfn *= selfn;
        uint4 v = H4[(size_t)warp * 16 + hl];
        const __half2* h2 = (const __half2*)&v;
#pragma unroll
        for (int j = 0; j < 4; j++) {
            float2 f = __half22float2(h2[j]);
            a[2 * j] = f.x * selfn;
            a[2 * j + 1] = f.y * selfn;
        }
    }

    int s = g_rowptr[warp];
    int e = s + g_cnt[warp];
    for (int p = s + half; p < e; p += 2) {
        int src = __ldg(&g_col[p]);
        float w = __ldg(&g_val[p]);
        uint4 v = __ldg(&H4[(size_t)src * 16 + hl]);
        const __half2* h2 = (const __half2*)&v;
#pragma unroll
        for (int j = 0; j < 4; j++) {
            float2 f = __half22float2(h2[j]);
            a[2 * j] += f.x * w;
            a[2 * j + 1] += f.y * w;
        }
    }
    __syncwarp();
#pragma unroll
    for (int j = 0; j < 8; j++)
        a[j] += __shfl_xor_sync(0xffffffffu, a[j], 16);
    if (half == 0) {
        __half2 h0 = __floats2half2_rn(a[0], a[1]);
        __half2 h1 = __floats2half2_rn(a[2], a[3]);
        __half2 h2o = __floats2half2_rn(a[4], a[5]);
        __half2 h3 = __floats2half2_rn(a[6], a[7]);
        uint4 pk;
        pk.x = *(unsigned*)&h0; pk.y = *(unsigned*)&h1;
        pk.z = *(unsigned*)&h2o; pk.w = *(unsigned*)&h3;
        ((uint4*)out)[(size_t)warp * 16 + hl] = pk;
    }
}

// ---------------- final aggregation at D=3 over g_proj ----------------
__global__ void k_agg3(float* __restrict__ out) {
    int v = blockIdx.x * blockDim.x + threadIdx.x;
    if (v >= N_NODES) return;
    float selfn = g_dis[v];
    selfn *= selfn;
    float4 p = g_proj[v];
    float a0 = p.x * selfn, a1 = p.y * selfn, a2 = p.z * selfn;

    int s = g_rowptr[v];
    int e = s + g_cnt[v];
#pragma unroll 2
    for (int q = s; q < e; q++) {
        int src = __ldg(&g_col[q]);
        float w = __ldg(&g_val[q]);
        float4 h = __ldg(&g_proj[src]);
        a0 += h.x * w; a1 += h.y * w; a2 += h.z * w;
    }
    out[(size_t)v * 3 + 0] = a0 + g_b45[0];
    out[(size_t)v * 3 + 1] = a1 + g_b45[1];
    out[(size_t)v * 3 + 2] = a2 + g_b45[2];
}

// ---------------- launch ----------------
extern "C" void kernel_launch(void* const* d_in, const int* in_sizes, int n_in,
                              void* d_out, int out_size) {
    const float* x    = (const float*)d_in[0];
    const void*  ei   = d_in[1];
    const float* ew   = (const float*)d_in[2];
    const float* W1   = (const float*)d_in[3];
    const float* b1   = (const float*)d_in[4];
    const float* W2   = (const float*)d_in[5];
    const float* b2   = (const float*)d_in[6];
    const float* W3   = (const float*)d_in[7];
    const float* b3   = (const float*)d_in[8];
    const float* W4   = (const float*)d_in[9];
    const float* b4   = (const float*)d_in[10];
    const float* Wout = (const float*)d_in[11];
    const float* bout = (const float*)d_in[12];
    float* out = (float*)d_out;

    __half *hx, *hA, *hB, *hW1, *hW2, *hW3;
    cudaGetSymbolAddress((void**)&hx, g_hx);
    cudaGetSymbolAddress((void**)&hA, g_hA);
    cudaGetSymbolAddress((void**)&hB, g_hB);
    cudaGetSymbolAddress((void**)&hW1, g_hW1);
    cudaGetSymbolAddress((void**)&hW2, g_hW2);
    cudaGetSymbolAddress((void**)&hW3, g_hW3);

    static cudaStream_t s2 = nullptr;
    static cudaEvent_t evFork = nullptr, evJoin = nullptr, evJoin2 = nullptr;
    if (!s2) {
        cudaStreamCreateWithFlags(&s2, cudaStreamNonBlocking);
        cudaEventCreateWithFlags(&evFork, cudaEventDisableTiming);
        cudaEventCreateWithFlags(&evJoin, cudaEventDisableTiming);
        cudaEventCreateWithFlags(&evJoin2, cudaEventDisableTiming);
    }

    const int TB = 256;
    int nodeBlocks = (N_NODES + TB - 1) / TB;
    int edge2Blocks = (N_EDGES / 2 + TB - 1) / TB;
    int warpNodeBlocks = (N_NODES + 7) / 8;
    int gm = (N_NODES + 127) / 128;
    int cvtBlocks = ((NX + 49152) / 8 + TB - 1) / TB;

    // fork: conversions + GEMM1 needed at first agg; W45 fold before fused GEMM3
    cudaEventRecord(evFork, 0);
    cudaStreamWaitEvent(s2, evFork, 0);
    k_cvtall<<<cvtBlocks, TB, 0, s2>>>(x, W1, W2, W3, hx, hW1, hW2, hW3);
    k_hgemm<<<dim3(gm, 1), 256, 0, s2>>>(hx, hW1, nullptr, hA, 128, 64, 0);
    cudaEventRecord(evJoin, s2);
    k_w45<<<97, 256, 0, s2>>>(W4, b4, Wout, bout);
    cudaEventRecord(evJoin2, s2);

    // main stream: CSR preprocessing (4 kernels, single-atomic degree pass)
    k_initdet<<<nodeBlocks, TB>>>((const long long*)ei);
    k_decdeg<<<edge2Blocks, TB>>>(ei, ew);
    k_disalloc<<<nodeBlocks, TB>>>();
    k_build<<<edge2Blocks, TB>>>(ei, ew);

    cudaStreamWaitEvent(0, evJoin, 0);

    // L1: h1 = relu(agg(t1) + b1)
    k_agg64<true, true><<<warpNodeBlocks, 256>>>(hA, b1, hB);

    // L2: h2 = relu(agg(h1) @ W2 + b2)
    k_agg64<false, false><<<warpNodeBlocks, 256>>>(hB, nullptr, hA);
    k_hgemm<<<dim3(gm, 2), 256>>>(hA, hW2, b2, hB, 64, 128, 1);

    // L3 + proj fused: g_proj = relu(agg(h2) @ W3 + b3) @ W45   (h3 never materialized)
    k_agg128<<<warpNodeBlocks, 256>>>(hB, hA);
    cudaStreamWaitEvent(0, evJoin2, 0);          // W45 ready
    k_hgemm_proj<<<dim3(gm, 4), 256>>>(hA, hW3, b3);

    // L4 head: out = agg(g_proj) + b45
    k_agg3<<<nodeBlocks, TB>>>(out);

    (void)in_sizes; (void)n_in; (void)out_size;
}

// round 14
// speedup vs baseline: 1.4462x; 1.4462x over previous
#include <cuda_runtime.h>
#include <cuda_fp16.h>
#include <mma.h>

using namespace nvcuda;

#define N_NODES 100000
#define N_EDGES 1600000

typedef unsigned long long ull;

// ---------------- scratch (__device__ globals; no allocation allowed) ----------------
__device__ float g_deg[N_NODES];
__device__ float g_dis[N_NODES];
__device__ int   g_cnt[N_NODES];
__device__ int   g_rowptr[N_NODES];
__device__ int   g_fill[N_NODES];
__device__ int   g_col[N_EDGES];
__device__ float g_val[N_EDGES];
__device__ int   g_is64;
__device__ int   g_total;
__device__ float g_W45[256 * 3];
__device__ float g_b45[3];
__device__ __half g_hx[(size_t)N_NODES * 128];
__device__ __half g_hA[(size_t)N_NODES * 256];
__device__ __half g_hB[(size_t)N_NODES * 256];
__device__ __half g_hW1[128 * 64];
__device__ __half g_hW2[64 * 128];
__device__ __half g_hW3[128 * 256];
__device__ float4 g_proj[N_NODES];

// ---------------- fused init + dtype detection + proj zero ----------------
__global__ void k_initdet(const long long* __restrict__ ei) {
    __shared__ int bigfound;
    int i = blockIdx.x * blockDim.x + threadIdx.x;
    if (i < N_NODES) {
        g_deg[i] = 1.0f;
        g_cnt[i] = 0;
        g_proj[i] = make_float4(0.f, 0.f, 0.f, 0.f);
    }
    if (blockIdx.x == 0) {
        if (threadIdx.x == 0) { bigfound = 0; g_total = 0; }
        __syncthreads();
        bool big = false;
#pragma unroll
        for (int j = 0; j < 8; j++) {
            ull v = (ull)ei[threadIdx.x * 8 + j];
            if (v >= (ull)N_NODES) big = true;
        }
        if (big) bigfound = 1;
        __syncthreads();
        if (threadIdx.x == 0) g_is64 = bigfound ? 0 : 1;
    }
}

__device__ __forceinline__ void decode_edge(const void* eiv, int e, int& s, int& d) {
    if (g_is64) {
        const long long* ei = (const long long*)eiv;
        s = (int)ei[e];
        d = (int)ei[N_EDGES + e];
    } else {
        const int* ei = (const int*)eiv;
        s = ei[e];
        d = ei[N_EDGES + e];
    }
}

__global__ void k_decdeg(const void* __restrict__ eiv, const float* __restrict__ ew) {
    int e = blockIdx.x * blockDim.x + threadIdx.x;
    if (e >= N_EDGES) return;
    int s, d;
    decode_edge(eiv, e, s, d);
    atomicAdd(&g_deg[d], ew[e]);
    atomicAdd(&g_cnt[d], 1);
}

// fused: dis = rsqrt(deg) AND CSR slot allocation (block scan + 1 atomic per block)
__global__ void k_disalloc() {
    __shared__ int s[256];
    __shared__ int sbase;
    int tid = threadIdx.x;
    int i = blockIdx.x * 256 + tid;
    int c = (i < N_NODES) ? g_cnt[i] : 0;
    if (i < N_NODES) g_dis[i] = rsqrtf(g_deg[i]);
    s[tid] = c;
    __syncthreads();
    for (int off = 1; off < 256; off <<= 1) {
        int t = (tid >= off) ? s[tid - off] : 0;
        __syncthreads();
        s[tid] += t;
        __syncthreads();
    }
    if (tid == 255) sbase = atomicAdd(&g_total, s[255]);
    __syncthreads();
    if (i < N_NODES) {
        int r = sbase + s[tid] - c;
        g_rowptr[i] = r;
        g_fill[i] = r;
    }
}

__global__ void k_build(const void* __restrict__ eiv, const float* __restrict__ ew) {
    int e = blockIdx.x * blockDim.x + threadIdx.x;
    if (e >= N_EDGES) return;
    int s, d;
    decode_edge(eiv, e, s, d);
    float nm = g_dis[s] * ew[e] * g_dis[d];
    int p = atomicAdd(&g_fill[d], 1);
    g_col[p] = s;
    g_val[p] = nm;
}

// parallel fold: W45[k][c] = sum_j W4[k][j] * Wout[j][c]; one warp per output
__global__ void k_w45(const float* __restrict__ W4, const float* __restrict__ b4,
                      const float* __restrict__ Wout, const float* __restrict__ bout) {
    int gw = (blockIdx.x * blockDim.x + threadIdx.x) >> 5;
    int lane = threadIdx.x & 31;
    if (gw < 768) {
        int k = gw / 3, c = gw % 3;
        float s = 0.f;
#pragma unroll
        for (int j = lane; j < 256; j += 32)
            s += W4[k * 256 + j] * Wout[j * 3 + c];
#pragma unroll
        for (int off = 16; off; off >>= 1)
            s += __shfl_down_sync(0xffffffffu, s, off);
        if (lane == 0) g_W45[gw] = s;
    } else if (gw < 771) {
        int c = gw - 768;
        float s = 0.f;
#pragma unroll
        for (int j = lane; j < 256; j += 32)
            s += b4[j] * Wout[j * 3 + c];
#pragma unroll
        for (int off = 16; off; off >>= 1)
            s += __shfl_down_sync(0xffffffffu, s, off);
        if (lane == 0) g_b45[c] = s + bout[c];
    }
}

// ---------------- fused fp32->fp16: x (12.8M) then W1/W2/W3 (49152) ----------------
#define NX (N_NODES * 128)
__global__ void k_cvtall(const float* __restrict__ x, const float* __restrict__ W1,
                         const float* __restrict__ W2, const float* __restrict__ W3,
                         __half* __restrict__ hx, __half* __restrict__ h1,
                         __half* __restrict__ h2, __half* __restrict__ h3) {
    int i = (blockIdx.x * blockDim.x + threadIdx.x) * 8;
    const float* in;
    __half* out;
    if (i < NX) { in = x; out = hx; }
    else {
        int w = i - NX;
        if (w < 8192) { in = W1; out = h1; i = w; }
        else if (w < 16384) { in = W2; out = h2; i = w - 8192; }
        else if (w < 49152) { in = W3; out = h3; i = w - 16384; }
        else return;
    }
    float4 a = *(const float4*)&in[i];
    float4 b = *(const float4*)&in[i + 4];
    __half2 q0 = __floats2half2_rn(a.x, a.y);
    __half2 q1 = __floats2half2_rn(a.z, a.w);
    __half2 q2 = __floats2half2_rn(b.x, b.y);
    __half2 q3 = __floats2half2_rn(b.z, b.w);
    uint4 pk;
    pk.x = *(unsigned*)&q0; pk.y = *(unsigned*)&q1;
    pk.z = *(unsigned*)&q2; pk.w = *(unsigned*)&q3;
    *(uint4*)&out[i] = pk;
}

// ---------------- HMMA GEMM (wmma): double-buffered, BK=32, fp16 output ----------------
__global__ void k_hgemm(const __half* __restrict__ A, const __half* __restrict__ W,
                        const float* __restrict__ bias, __half* __restrict__ C,
                        int din, int dout, int relu) {
    __shared__ __half As[2][128][40];
    __shared__ __half Bs[2][32][72];
    __shared__ float Es[8][256];

    int tid = threadIdx.x;
    int lane = tid & 31;
    int wid = tid >> 5;
    int warp_m = wid & 3;
    int warp_n = wid >> 2;
    int row0 = blockIdx.x * 128;
    int col0 = blockIdx.y * 64;

    int ar0 = tid >> 1, ac0 = (tid & 1) * 8;
    int br = tid >> 3, bc = (tid & 7) * 8;

    wmma::fragment<wmma::accumulator, 16, 16, 16, float> acc[2][2];
#pragma unroll
    for (int i = 0; i < 2; i++)
#pragma unroll
        for (int j = 0; j < 2; j++) wmma::fill_fragment(acc[i][j], 0.f);

    int nk = din >> 5;

    {
        uint4 v0 = make_uint4(0, 0, 0, 0), v1 = v0;
        if (row0 + ar0 < N_NODES) {
            v0 = *(const uint4*)&A[(size_t)(row0 + ar0) * din + ac0];
            v1 = *(const uint4*)&A[(size_t)(row0 + ar0) * din + ac0 + 16];
        }
        *(uint4*)&As[0][ar0][ac0] = v0;
        *(uint4*)&As[0][ar0][ac0 + 16] = v1;
        *(uint4*)&Bs[0][br][bc] = *(const uint4*)&W[(size_t)br * dout + col0 + bc];
    }
    __syncthreads();

    for (int kt = 0; kt < nk; kt++) {
        int cur = kt & 1;
        bool more = (kt + 1 < nk);
        uint4 p0, p1, pb;
        if (more) {
            int k0 = (kt + 1) << 5;
            p0 = make_uint4(0, 0, 0, 0); p1 = p0;
            if (row0 + ar0 < N_NODES) {
                p0 = *(const uint4*)&A[(size_t)(row0 + ar0) * din + k0 + ac0];
                p1 = *(const uint4*)&A[(size_t)(row0 + ar0) * din + k0 + ac0 + 16];
            }
            pb = *(const uint4*)&W[(size_t)(k0 + br) * dout + col0 + bc];
        }
#pragma unroll
        for (int ks = 0; ks < 2; ks++) {
            wmma::fragment<wmma::matrix_a, 16, 16, 16, __half, wmma::row_major> af[2];
            wmma::fragment<wmma::matrix_b, 16, 16, 16, __half, wmma::row_major> bf[2];
#pragma unroll
            for (int i = 0; i < 2; i++)
                wmma::load_matrix_sync(af[i], &As[cur][warp_m * 32 + i * 16][ks * 16], 40);
#pragma unroll
            for (int j = 0; j < 2; j++)
                wmma::load_matrix_sync(bf[j], &Bs[cur][ks * 16][warp_n * 32 + j * 16], 72);
#pragma unroll
            for (int i = 0; i < 2; i++)
#pragma unroll
                for (int j = 0; j < 2; j++)
                    wmma::mma_sync(acc[i][j], af[i], bf[j], acc[i][j]);
        }
        if (more) {
            int nxt = cur ^ 1;
            *(uint4*)&As[nxt][ar0][ac0] = p0;
            *(uint4*)&As[nxt][ar0][ac0 + 16] = p1;
            *(uint4*)&Bs[nxt][br][bc] = pb;
            __syncthreads();
        }
    }

#pragma unroll
    for (int i = 0; i < 2; i++) {
#pragma unroll
        for (int j = 0; j < 2; j++) {
            wmma::store_matrix_sync(&Es[wid][0], acc[i][j], 16, wmma::mem_row_major);
            __syncwarp();
            int r = lane >> 1, c = (lane & 1) * 8;
            int gr = row0 + warp_m * 32 + i * 16 + r;
            int gc = col0 + warp_n * 32 + j * 16 + c;
            if (gr < N_NODES) {
                float v[8];
#pragma unroll
                for (int t = 0; t < 8; t++) {
                    float f = Es[wid][r * 16 + c + t];
                    if (bias) f += bias[gc + t];
                    if (relu) f = fmaxf(f, 0.f);
                    v[t] = f;
                }
                __half2 h0 = __floats2half2_rn(v[0], v[1]);
                __half2 h1 = __floats2half2_rn(v[2], v[3]);
                __half2 h2 = __floats2half2_rn(v[4], v[5]);
                __half2 h3 = __floats2half2_rn(v[6], v[7]);
                uint4 pk;
                pk.x = *(unsigned*)&h0; pk.y = *(unsigned*)&h1;
                pk.z = *(unsigned*)&h2; pk.w = *(unsigned*)&h3;
                *(uint4*)&C[(size_t)gr * dout + gc] = pk;
            }
            __syncwarp();
        }
    }
}

// ---------------- GEMM3 fused with projection: (relu(A@W3+b3)) @ W45 -> atomicAdd g_proj ----------------
__global__ void k_hgemm_proj(const __half* __restrict__ A, const __half* __restrict__ W,
                             const float* __restrict__ bias) {
    const int din = 128, dout = 256;
    __shared__ __half As[2][128][40];
    __shared__ __half Bs[2][32][72];
    __shared__ float Es[8][256];

    int tid = threadIdx.x;
    int lane = tid & 31;
    int wid = tid >> 5;
    int warp_m = wid & 3;
    int warp_n = wid >> 2;
    int row0 = blockIdx.x * 128;
    int col0 = blockIdx.y * 64;

    int ar0 = tid >> 1, ac0 = (tid & 1) * 8;
    int br = tid >> 3, bc = (tid & 7) * 8;

    wmma::fragment<wmma::accumulator, 16, 16, 16, float> acc[2][2];
#pragma unroll
    for (int i = 0; i < 2; i++)
#pragma unroll
        for (int j = 0; j < 2; j++) wmma::fill_fragment(acc[i][j], 0.f);

    int nk = din >> 5;

    {
        uint4 v0 = make_uint4(0, 0, 0, 0), v1 = v0;
        if (row0 + ar0 < N_NODES) {
            v0 = *(const uint4*)&A[(size_t)(row0 + ar0) * din + ac0];
            v1 = *(const uint4*)&A[(size_t)(row0 + ar0) * din + ac0 + 16];
        }
        *(uint4*)&As[0][ar0][ac0] = v0;
        *(uint4*)&As[0][ar0][ac0 + 16] = v1;
        *(uint4*)&Bs[0][br][bc] = *(const uint4*)&W[(size_t)br * dout + col0 + bc];
    }
    __syncthreads();

    for (int kt = 0; kt < nk; kt++) {
        int cur = kt & 1;
        bool more = (kt + 1 < nk);
        uint4 p0, p1, pb;
        if (more) {
            int k0 = (kt + 1) << 5;
            p0 = make_uint4(0, 0, 0, 0); p1 = p0;
            if (row0 + ar0 < N_NODES) {
                p0 = *(const uint4*)&A[(size_t)(row0 + ar0) * din + k0 + ac0];
                p1 = *(const uint4*)&A[(size_t)(row0 + ar0) * din + k0 + ac0 + 16];
            }
            pb = *(const uint4*)&W[(size_t)(k0 + br) * dout + col0 + bc];
        }
#pragma unroll
        for (int ks = 0; ks < 2; ks++) {
            wmma::fragment<wmma::matrix_a, 16, 16, 16, __half, wmma::row_major> af[2];
            wmma::fragment<wmma::matrix_b, 16, 16, 16, __half, wmma::row_major> bf[2];
#pragma unroll
            for (int i = 0; i < 2; i++)
                wmma::load_matrix_sync(af[i], &As[cur][warp_m * 32 + i * 16][ks * 16], 40);
#pragma unroll
            for (int j = 0; j < 2; j++)
                wmma::load_matrix_sync(bf[j], &Bs[cur][ks * 16][warp_n * 32 + j * 16], 72);
#pragma unroll
            for (int i = 0; i < 2; i++)
#pragma unroll
                for (int j = 0; j < 2; j++)
                    wmma::mma_sync(acc[i][j], af[i], bf[j], acc[i][j]);
        }
        if (more) {
            int nxt = cur ^ 1;
            *(uint4*)&As[nxt][ar0][ac0] = p0;
            *(uint4*)&As[nxt][ar0][ac0 + 16] = p1;
            *(uint4*)&Bs[nxt][br][bc] = pb;
            __syncthreads();
        }
    }

    // epilogue: bias + relu + project 64 cols against W45, atomic accumulate
    int r = lane >> 1, cbase = (lane & 1) * 8;
#pragma unroll
    for (int i = 0; i < 2; i++) {
        float s0 = 0.f, s1 = 0.f, s2 = 0.f;
        int gr = row0 + warp_m * 32 + i * 16 + r;
#pragma unroll
        for (int j = 0; j < 2; j++) {
            wmma::store_matrix_sync(&Es[wid][0], acc[i][j], 16, wmma::mem_row_major);
            __syncwarp();
            int gc = col0 + warp_n * 32 + j * 16 + cbase;
#pragma unroll
            for (int t = 0; t < 8; t++) {
                float f = Es[wid][r * 16 + cbase + t] + bias[gc + t];
                f = fmaxf(f, 0.f);
                s0 += f * g_W45[(gc + t) * 3 + 0];
                s1 += f * g_W45[(gc + t) * 3 + 1];
                s2 += f * g_W45[(gc + t) * 3 + 2];
            }
            __syncwarp();
        }
        s0 += __shfl_xor_sync(0xffffffffu, s0, 1);
        s1 += __shfl_xor_sync(0xffffffffu, s1, 1);
        s2 += __shfl_xor_sync(0xffffffffu, s2, 1);
        if ((lane & 1) == 0 && gr < N_NODES) {
            atomicAdd(&g_proj[gr].x, s0);
            atomicAdd(&g_proj[gr].y, s1);
            atomicAdd(&g_proj[gr].z, s2);
        }
    }
}

// ---------------- aggregation D=64 fp16: 4 edges per warp (8 lanes x 16B each) ----------------
template <bool BIAS, bool RELU>
__global__ void k_agg64(const __half* __restrict__ H, const float* __restrict__ bias,
                        __half* __restrict__ out) {
    int warp = (blockIdx.x * blockDim.x + threadIdx.x) >> 5;
    int lane = threadIdx.x & 31;
    if (warp >= N_NODES) return;
    int grp = lane >> 3, gl = lane & 7;
    const uint4* H4 = (const uint4*)H;

    float a[8];
#pragma unroll
    for (int j = 0; j < 8; j++) a[j] = 0.f;

    if (grp == 0) {
        float selfn = g_dis[warp];
        selfn *= selfn;
        uint4 v = H4[(size_t)warp * 8 + gl];
        const __half2* h2 = (const __half2*)&v;
#pragma unroll
        for (int j = 0; j < 4; j++) {
            float2 f = __half22float2(h2[j]);
            a[2 * j] = f.x * selfn;
            a[2 * j + 1] = f.y * selfn;
        }
    }

    int s = g_rowptr[warp];
    int e = s + g_cnt[warp];
    for (int p = s + grp; p < e; p += 4) {
        int src = __ldg(&g_col[p]);
        float w = __ldg(&g_val[p]);
        uint4 v = __ldg(&H4[(size_t)src * 8 + gl]);
        const __half2* h2 = (const __half2*)&v;
#pragma unroll
        for (int j = 0; j < 4; j++) {
            float2 f = __half22float2(h2[j]);
            a[2 * j] += f.x * w;
            a[2 * j + 1] += f.y * w;
        }
    }
    __syncwarp();
#pragma unroll
    for (int j = 0; j < 8; j++) {
        a[j] += __shfl_xor_sync(0xffffffffu, a[j], 8);
        a[j] += __shfl_xor_sync(0xffffffffu, a[j], 16);
    }
    if (grp == 0) {
#pragma unroll
        for (int j = 0; j < 8; j++) {
            if (BIAS) a[j] += bias[gl * 8 + j];
            if (RELU) a[j] = fmaxf(a[j], 0.f);
        }
        __half2 h0 = __floats2half2_rn(a[0], a[1]);
        __half2 h1 = __floats2half2_rn(a[2], a[3]);
        __half2 h2o = __floats2half2_rn(a[4], a[5]);
        __half2 h3 = __floats2half2_rn(a[6], a[7]);
        uint4 pk;
        pk.x = *(unsigned*)&h0; pk.y = *(unsigned*)&h1;
        pk.z = *(unsigned*)&h2o; pk.w = *(unsigned*)&h3;
        ((uint4*)out)[(size_t)warp * 8 + gl] = pk;
    }
}

// ---------------- aggregation D=128 fp16 in/out: 2 edges per warp (16 lanes x 16B) ----------------
__global__ void k_agg128(const __half* __restrict__ H, __half* __restrict__ out) {
    int warp = (blockIdx.x * blockDim.x + threadIdx.x) >> 5;
    int lane = threadIdx.x & 31;
    if (warp >= N_NODES) return;
    int half = lane >> 4, hl = lane & 15;
    const uint4* H4 = (const uint4*)H;

    float a[8];
#pragma unroll
    for (int j = 0; j < 8; j++) a[j] = 0.f;

    if (half == 0) {
        float selfn = g_dis[warp];
        selfn *= selfn;
        uint4 v = H4[(size_t)warp * 16 + hl];
        const __half2* h2 = (const __half2*)&v;
#pragma unroll
        for (int j = 0; j < 4; j++) {
            float2 f = __half22float2(h2[j]);
            a[2 * j] = f.x * selfn;
            a[2 * j + 1] = f.y * selfn;
        }
    }

    int s = g_rowptr[warp];
    int e = s + g_cnt[warp];
    for (int p = s + half; p < e; p += 2) {
        int src = __ldg(&g_col[p]);
        float w = __ldg(&g_val[p]);
        uint4 v = __ldg(&H4[(size_t)src * 16 + hl]);
        const __half2* h2 = (const __half2*)&v;
#pragma unroll
        for (int j = 0; j < 4; j++) {
            float2 f = __half22float2(h2[j]);
            a[2 * j] += f.x * w;
            a[2 * j + 1] += f.y * w;
        }
    }
    __syncwarp();
#pragma unroll
    for (int j = 0; j < 8; j++)
        a[j] += __shfl_xor_sync(0xffffffffu, a[j], 16);
    if (half == 0) {
        __half2 h0 = __floats2half2_rn(a[0], a[1]);
        __half2 h1 = __floats2half2_rn(a[2], a[3]);
        __half2 h2o = __floats2half2_rn(a[4], a[5]);
        __half2 h3 = __floats2half2_rn(a[6], a[7]);
        uint4 pk;
        pk.x = *(unsigned*)&h0; pk.y = *(unsigned*)&h1;
        pk.z = *(unsigned*)&h2o; pk.w = *(unsigned*)&h3;
        ((uint4*)out)[(size_t)warp * 16 + hl] = pk;
    }
}

// ---------------- final aggregation at D=3 over g_proj ----------------
__global__ void k_agg3(float* __restrict__ out) {
    int v = blockIdx.x * blockDim.x + threadIdx.x;
    if (v >= N_NODES) return;
    float selfn = g_dis[v];
    selfn *= selfn;
    float4 p = g_proj[v];
    float a0 = p.x * selfn, a1 = p.y * selfn, a2 = p.z * selfn;

    int s = g_rowptr[v];
    int e = s + g_cnt[v];
#pragma unroll 2
    for (int q = s; q < e; q++) {
        int src = __ldg(&g_col[q]);
        float w = __ldg(&g_val[q]);
        float4 h = __ldg(&g_proj[src]);
        a0 += h.x * w; a1 += h.y * w; a2 += h.z * w;
    }
    out[(size_t)v * 3 + 0] = a0 + g_b45[0];
    out[(size_t)v * 3 + 1] = a1 + g_b45[1];
    out[(size_t)v * 3 + 2] = a2 + g_b45[2];
}

// ---------------- launch ----------------
extern "C" void kernel_launch(void* const* d_in, const int* in_sizes, int n_in,
                              void* d_out, int out_size) {
    const float* x    = (const float*)d_in[0];
    const void*  ei   = d_in[1];
    const float* ew   = (const float*)d_in[2];
    const float* W1   = (const float*)d_in[3];
    const float* b1   = (const float*)d_in[4];
    const float* W2   = (const float*)d_in[5];
    const float* b2   = (const float*)d_in[6];
    const float* W3   = (const float*)d_in[7];
    const float* b3   = (const float*)d_in[8];
    const float* W4   = (const float*)d_in[9];
    const float* b4   = (const float*)d_in[10];
    const float* Wout = (const float*)d_in[11];
    const float* bout = (const float*)d_in[12];
    float* out = (float*)d_out;

    __half *hx, *hA, *hB, *hW1, *hW2, *hW3;
    cudaGetSymbolAddress((void**)&hx, g_hx);
    cudaGetSymbolAddress((void**)&hA, g_hA);
    cudaGetSymbolAddress((void**)&hB, g_hB);
    cudaGetSymbolAddress((void**)&hW1, g_hW1);
    cudaGetSymbolAddress((void**)&hW2, g_hW2);
    cudaGetSymbolAddress((void**)&hW3, g_hW3);

    static cudaStream_t s2 = nullptr;
    static cudaEvent_t evFork = nullptr, evJoin = nullptr, evJoin2 = nullptr;
    if (!s2) {
        cudaStreamCreateWithFlags(&s2, cudaStreamNonBlocking);
        cudaEventCreateWithFlags(&evFork, cudaEventDisableTiming);
        cudaEventCreateWithFlags(&evJoin, cudaEventDisableTiming);
        cudaEventCreateWithFlags(&evJoin2, cudaEventDisableTiming);
    }

    const int TB = 256;
    int nodeBlocks = (N_NODES + TB - 1) / TB;
    int edgeBlocks = (N_EDGES + TB - 1) / TB;
    int warpNodeBlocks = (N_NODES + 7) / 8;
    int gm = (N_NODES + 127) / 128;
    int cvtBlocks = ((NX + 49152) / 8 + TB - 1) / TB;

    // fork: conversions + GEMM1 needed at first agg; W45 fold before fused GEMM3
    cudaEventRecord(evFork, 0);
    cudaStreamWaitEvent(s2, evFork, 0);
    k_cvtall<<<cvtBlocks, TB, 0, s2>>>(x, W1, W2, W3, hx, hW1, hW2, hW3);
    k_hgemm<<<dim3(gm, 1), 256, 0, s2>>>(hx, hW1, nullptr, hA, 128, 64, 0);
    cudaEventRecord(evJoin, s2);
    k_w45<<<97, 256, 0, s2>>>(W4, b4, Wout, bout);
    cudaEventRecord(evJoin2, s2);

    // main stream: CSR preprocessing (4 kernels)
    k_initdet<<<nodeBlocks, TB>>>((const long long*)ei);
    k_decdeg<<<edgeBlocks, TB>>>(ei, ew);
    k_disalloc<<<nodeBlocks, TB>>>();
    k_build<<<edgeBlocks, TB>>>(ei, ew);

    cudaStreamWaitEvent(0, evJoin, 0);

    // L1: h1 = relu(agg(t1) + b1)
    k_agg64<true, true><<<warpNodeBlocks, 256>>>(hA, b1, hB);

    // L2: h2 = relu(agg(h1) @ W2 + b2)
    k_agg64<false, false><<<warpNodeBlocks, 256>>>(hB, nullptr, hA);
    k_hgemm<<<dim3(gm, 2), 256>>>(hA, hW2, b2, hB, 64, 128, 1);

    // L3 + proj fused: g_proj = relu(agg(h2) @ W3 + b3) @ W45   (h3 never materialized)
    k_agg128<<<warpNodeBlocks, 256>>>(hB, hA);
    cudaStreamWaitEvent(0, evJoin2, 0);          // W45 ready
    k_hgemm_proj<<<dim3(gm, 4), 256>>>(hA, hW3, b3);

    // L4 head: out = agg(g_proj) + b45
    k_agg3<<<nodeBlocks, TB>>>(out);

    (void)in_sizes; (void)n_in; (void)out_size;
}